// round 8
// baseline (speedup 1.0000x reference)
#include <cuda_runtime.h>
#include <cuda_bf16.h>
#include <cstdint>

// Problem constants (GCNEncoder_55052890800619)
#define NN 100000
#define DD 128
#define HH 256
#define EE 1600000

typedef unsigned short ushort_t;

// ---------------- scratch (device globals; no allocations allowed) ----------
__device__ int   g_is64;
__device__ int   g_cnt[NN];
__device__ int   g_rowptr[NN];
__device__ int   g_cursor[NN];
__device__ float g_dinv[NN];
__device__ int   g_bsums[128];
__device__ __align__(16) int2 g_csr[EE];                        // 12.8 MB
// W images: n-major, kpair-permuted bf16 hi/lo
__device__ __align__(16) ushort_t g_w1h[DD * HH];               // 64 KB each
__device__ __align__(16) ushort_t g_w1l[DD * HH];
__device__ __align__(16) ushort_t g_w2h[HH * DD];
__device__ __align__(16) ushort_t g_w2l[HH * DD];
// A operands: row-major bf16x2, kpair-permuted (fragment-ready)
__device__ __align__(16) uint32_t g_a1h[(size_t)NN * (DD / 2)]; // 25.6 MB
__device__ __align__(16) uint32_t g_a1l[(size_t)NN * (DD / 2)];
__device__ __align__(16) uint32_t g_a2h[(size_t)NN * (HH / 2)]; // 51.2 MB
__device__ __align__(16) uint32_t g_a2l[(size_t)NN * (HH / 2)];
__device__ __align__(16) float    g_xw2[(size_t)NN * DD];       // 51.2 MB

// kpair -> permuted column: within each group of 8 kpairs (k16 step), place
// kpairs (t, t+4) adjacently so an mma fragment load is one LDS.64.
__device__ __forceinline__ int pcol(int kp) {
    return (kp & ~7) + ((kp & 3) << 1) + ((kp >> 2) & 1);
}

// ---------------- prep kernels ----------------------------------------------
__global__ void zero_detect_kernel(const unsigned int* __restrict__ p, int n) {
    int i = blockIdx.x * blockDim.x + threadIdx.x;
    if (i < n) g_cnt[i] = 0;
    if (blockIdx.x == 0 && threadIdx.x < 32) {
        int any = 0;
        #pragma unroll
        for (int q = 0; q < 2; q++) {
            long long j = (long long)(threadIdx.x * 2 + q) * 24999 + 7;
            any |= (p[2 * j + 1] != 0u);
        }
        any = __any_sync(0xffffffffu, any);
        if (threadIdx.x == 0) g_is64 = any ? 0 : 1;
    }
}

__device__ __forceinline__ int2 load_edge(const void* eptr, int E, int e, int is64) {
    int2 r;
    if (is64) {
        const long long* q = (const long long*)eptr;
        r.x = (int)q[e];
        r.y = (int)q[(size_t)E + e];
    } else {
        const int* q = (const int*)eptr;
        r.x = q[e];
        r.y = q[(size_t)E + e];
    }
    return r;
}

__global__ void count_kernel(const void* __restrict__ eptr, int E) {
    int e = blockIdx.x * blockDim.x + threadIdx.x;
    if (e >= E) return;
    int d;
    if (g_is64) d = (int)(((const long long*)eptr)[(size_t)E + e]);
    else        d = ((const int*)eptr)[(size_t)E + e];
    atomicAdd(&g_cnt[d], 1);
}

__global__ void scanblock_dinv_kernel(int n) {
    __shared__ int sh[1024];
    int gid = blockIdx.x * 1024 + threadIdx.x;
    int v = (gid < n) ? g_cnt[gid] : 0;
    if (gid < n) g_dinv[gid] = rsqrtf((float)v + 1.0f);
    sh[threadIdx.x] = v;
    __syncthreads();
    for (int off = 1; off < 1024; off <<= 1) {
        int t = (threadIdx.x >= (unsigned)off) ? sh[threadIdx.x - off] : 0;
        __syncthreads();
        sh[threadIdx.x] += t;
        __syncthreads();
    }
    if (gid < n) g_rowptr[gid] = sh[threadIdx.x] - v;
    if (threadIdx.x == 1023) g_bsums[blockIdx.x] = sh[1023];
}

__global__ void add_offsets_kernel(int n, int nb) {
    __shared__ int sh[128];
    int tid = threadIdx.x;
    if (tid < 128) sh[tid] = (tid < nb) ? g_bsums[tid] : 0;
    __syncthreads();
    for (int off = 1; off < 128; off <<= 1) {
        int t = (tid >= (unsigned)off && tid < 128) ? sh[tid - off] : 0;
        __syncthreads();
        if (tid < 128) sh[tid] += t;
        __syncthreads();
    }
    int i = blockIdx.x * 256 + tid;
    if (i >= n) return;
    int j = i >> 10;
    int off = (j == 0) ? 0 : sh[j - 1];
    int r = g_rowptr[i] + off;
    g_rowptr[i] = r;
    g_cursor[i] = r;
}

__global__ void csr_fill_kernel(const void* __restrict__ eptr, int E) {
    int e = blockIdx.x * blockDim.x + threadIdx.x;
    if (e >= E) return;
    int2 sd = load_edge(eptr, E, e, g_is64);
    int pos = atomicAdd(&g_cursor[sd.y], 1);
    float w = g_dinv[sd.x] * g_dinv[sd.y];
    g_csr[pos] = make_int2(sd.x, __float_as_int(w));
}

// ---------------- bf16 split helpers ----------------------------------------
__device__ __forceinline__ void split_pack(float x0, float x1,
                                           uint32_t& hi, uint32_t& lo) {
    uint32_t h;
    asm("cvt.rn.bf16x2.f32 %0, %1, %2;" : "=r"(h) : "f"(x1), "f"(x0));
    float e0 = x0 - __uint_as_float(h << 16);
    float e1 = x1 - __uint_as_float(h & 0xffff0000u);
    asm("cvt.rn.bf16x2.f32 %0, %1, %2;" : "=r"(lo) : "f"(e1), "f"(e0));
    hi = h;
}

__device__ __forceinline__ void mma16(float* c, const uint32_t* a, const uint32_t* b) {
    asm volatile(
        "mma.sync.aligned.m16n8k16.row.col.f32.bf16.bf16.f32 "
        "{%0,%1,%2,%3}, {%4,%5,%6,%7}, {%8,%9}, {%0,%1,%2,%3};"
        : "+f"(c[0]), "+f"(c[1]), "+f"(c[2]), "+f"(c[3])
        : "r"(a[0]), "r"(a[1]), "r"(a[2]), "r"(a[3]), "r"(b[0]), "r"(b[1]));
}

// ---------------- W pre-convert: n-major kpair-permuted hi/lo image ----------
// W input row-major [K][N]; output: oh[n*K + pcol(k/2)*2 + (k&1)]
__global__ void convert_w_kernel(const float* __restrict__ W,
                                 ushort_t* __restrict__ oh,
                                 ushort_t* __restrict__ ol,
                                 int N, int K)
{
    int idx = blockIdx.x * blockDim.x + threadIdx.x;
    if (idx >= N * K) return;
    int k = idx / N, n = idx % N;
    float v = W[idx];
    uint32_t h, l;
    split_pack(v, 0.f, h, l);
    int o = n * K + pcol(k >> 1) * 2 + (k & 1);
    oh[o] = (ushort_t)(h & 0xffff);
    ol[o] = (ushort_t)(l & 0xffff);
}

// ---------------- GEMM: pre-split bf16 operands, mma.sync --------------------
// C[M, TN] = A[M, TK] @ B[TK, TN]; block 128(m) x 128(n), BK=16, 8 warps,
// warp tile 64x32.  A: row-major permuted bf16x2 hi/lo.  B: n-major permuted
// ushort image.  SPLIT_OUT: emit relu(acc+bias) as permuted hi/lo bf16x2.
#define GSTR 10

template <int TK, int TN, bool SPLIT_OUT>
__global__ void __launch_bounds__(256, 2)
gemm_pre(const uint32_t* __restrict__ Ah, const uint32_t* __restrict__ Al,
         const ushort_t* __restrict__ Bh, const ushort_t* __restrict__ Bl,
         const float* __restrict__ bias,
         float* __restrict__ Cf, uint32_t* __restrict__ Ch,
         uint32_t* __restrict__ Cl, int M)
{
    __shared__ uint32_t Ahi[128][GSTR], Alo[128][GSTR];
    __shared__ uint32_t Bhi[128][GSTR], Blo[128][GSTR];

    const int tid  = threadIdx.x;
    const int wid  = tid >> 5;
    const int lane = tid & 31;
    const int g    = lane >> 2;
    const int t    = lane & 3;
    const int brow = blockIdx.y * 128;
    const int bcol = blockIdx.x * 128;
    const int wm   = (wid >> 2) * 64;   // 0 or 64
    const int wn   = (wid & 3) * 32;    // 0,32,64,96

    const int lm   = tid >> 1;          // loader row 0..127
    const int part = tid & 1;           // which uint4 of the 8-col group

    float acc[4][4][4];
    #pragma unroll
    for (int mt = 0; mt < 4; mt++)
        #pragma unroll
        for (int nt = 0; nt < 4; nt++)
            #pragma unroll
            for (int i = 0; i < 4; i++) acc[mt][nt][i] = 0.0f;

    for (int grp = 0; grp < TK / 16; grp++) {
        // --- A tile: one uint4 (hi) + one (lo) per thread
        {
            int row = brow + lm;
            uint4 vh = make_uint4(0, 0, 0, 0), vl = make_uint4(0, 0, 0, 0);
            if (row < M) {
                size_t off = (size_t)row * (TK / 2) + grp * 8 + part * 4;
                vh = *(const uint4*)(Ah + off);
                vl = *(const uint4*)(Al + off);
            }
            int c = part * 4;
            Ahi[lm][c + 0] = vh.x; Ahi[lm][c + 1] = vh.y;
            Ahi[lm][c + 2] = vh.z; Ahi[lm][c + 3] = vh.w;
            Alo[lm][c + 0] = vl.x; Alo[lm][c + 1] = vl.y;
            Alo[lm][c + 2] = vl.z; Alo[lm][c + 3] = vl.w;
        }
        // --- B tile: one uint4 (hi) + one (lo) per thread (n-major image)
        {
            size_t off = (size_t)(bcol + lm) * TK + grp * 16 + part * 8;
            uint4 vh = *(const uint4*)(Bh + off);
            uint4 vl = *(const uint4*)(Bl + off);
            int c = part * 4;
            Bhi[lm][c + 0] = vh.x; Bhi[lm][c + 1] = vh.y;
            Bhi[lm][c + 2] = vh.z; Bhi[lm][c + 3] = vh.w;
            Blo[lm][c + 0] = vl.x; Blo[lm][c + 1] = vl.y;
            Blo[lm][c + 2] = vl.z; Blo[lm][c + 3] = vl.w;
        }
        __syncthreads();

        {
            const int cb = 2 * t;
            uint32_t ah[4][4], al[4][4];
            #pragma unroll
            for (int mt = 0; mt < 4; mt++) {
                int r = wm + mt * 16;
                uint2 p0 = *(const uint2*)&Ahi[r + g    ][cb];
                uint2 p1 = *(const uint2*)&Ahi[r + g + 8][cb];
                ah[mt][0] = p0.x; ah[mt][2] = p0.y;
                ah[mt][1] = p1.x; ah[mt][3] = p1.y;
                uint2 q0 = *(const uint2*)&Alo[r + g    ][cb];
                uint2 q1 = *(const uint2*)&Alo[r + g + 8][cb];
                al[mt][0] = q0.x; al[mt][2] = q0.y;
                al[mt][1] = q1.x; al[mt][3] = q1.y;
            }
            #pragma unroll
            for (int nt = 0; nt < 4; nt++) {
                uint2 bh2 = *(const uint2*)&Bhi[wn + nt * 8 + g][cb];
                uint2 bl2 = *(const uint2*)&Blo[wn + nt * 8 + g][cb];
                uint32_t bh[2] = {bh2.x, bh2.y};
                uint32_t bl[2] = {bl2.x, bl2.y};
                #pragma unroll
                for (int mt = 0; mt < 4; mt++) {
                    mma16(acc[mt][nt], ah[mt], bh);
                    mma16(acc[mt][nt], ah[mt], bl);
                    mma16(acc[mt][nt], al[mt], bh);
                }
            }
        }
        __syncthreads();
    }

    // ---- epilogue ----
    #pragma unroll
    for (int nt = 0; nt < 4; nt++) {
        int n0 = bcol + wn + nt * 8 + 2 * t;
        #pragma unroll
        for (int mt = 0; mt < 4; mt++) {
            int r0 = brow + wm + mt * 16 + g;
            if (SPLIT_OUT) {
                float b0 = bias[n0], b1 = bias[n0 + 1];
                int pc = pcol(n0 >> 1);
                if (r0 < M) {
                    float v0 = fmaxf(acc[mt][nt][0] + b0, 0.f);
                    float v1 = fmaxf(acc[mt][nt][1] + b1, 0.f);
                    uint32_t h, l;
                    split_pack(v0, v1, h, l);
                    size_t ob = (size_t)r0 * (TN / 2) + pc;
                    Ch[ob] = h; Cl[ob] = l;
                }
                if (r0 + 8 < M) {
                    float v0 = fmaxf(acc[mt][nt][2] + b0, 0.f);
                    float v1 = fmaxf(acc[mt][nt][3] + b1, 0.f);
                    uint32_t h, l;
                    split_pack(v0, v1, h, l);
                    size_t ob = (size_t)(r0 + 8) * (TN / 2) + pc;
                    Ch[ob] = h; Cl[ob] = l;
                }
            } else {
                if (r0 < M)
                    *(float2*)(Cf + (size_t)r0 * TN + n0) =
                        make_float2(acc[mt][nt][0], acc[mt][nt][1]);
                if (r0 + 8 < M)
                    *(float2*)(Cf + (size_t)(r0 + 8) * TN + n0) =
                        make_float2(acc[mt][nt][2], acc[mt][nt][3]);
            }
        }
    }
}

// ---------------- agg layer 1: gather emb, emit permuted hi/lo bf16x2 --------
__global__ void __launch_bounds__(256)
agg_split(const float* __restrict__ xw, int n)
{
    int node = (blockIdx.x * 256 + threadIdx.x) >> 5;
    int lane = threadIdx.x & 31;
    if (node >= n) return;

    float dsq = g_dinv[node];
    dsq *= dsq;
    const float4* base = (const float4*)xw;
    float4 tv = base[(size_t)node * 32 + lane];
    float4 acc = make_float4(tv.x * dsq, tv.y * dsq, tv.z * dsq, tv.w * dsq);

    int j   = g_rowptr[node];
    int end = j + g_cnt[node];
    for (; j + 8 <= end; j += 8) {
        int2 e[8];
        #pragma unroll
        for (int q = 0; q < 8; q++) e[q] = g_csr[j + q];
        float4 p[8];
        #pragma unroll
        for (int q = 0; q < 8; q++) p[q] = base[(size_t)e[q].x * 32 + lane];
        #pragma unroll
        for (int q = 0; q < 8; q++) {
            float w = __int_as_float(e[q].y);
            acc.x = fmaf(p[q].x, w, acc.x); acc.y = fmaf(p[q].y, w, acc.y);
            acc.z = fmaf(p[q].z, w, acc.z); acc.w = fmaf(p[q].w, w, acc.w);
        }
    }
    for (; j < end; j++) {
        int2 e = g_csr[j];
        float w = __int_as_float(e.y);
        float4 p = base[(size_t)e.x * 32 + lane];
        acc.x = fmaf(p.x, w, acc.x); acc.y = fmaf(p.y, w, acc.y);
        acc.z = fmaf(p.z, w, acc.z); acc.w = fmaf(p.w, w, acc.w);
    }

    uint32_t h0, l0, h1, l1;
    split_pack(acc.x, acc.y, h0, l0);   // kpair 2*lane
    split_pack(acc.z, acc.w, h1, l1);   // kpair 2*lane+1
    size_t rb = (size_t)node * 64;
    int c0 = pcol(2 * lane), c1 = pcol(2 * lane + 1);
    g_a1h[rb + c0] = h0; g_a1l[rb + c0] = l0;
    g_a1h[rb + c1] = h1; g_a1l[rb + c1] = l1;
}

// ---------------- agg layer 2 (fp32, + bias) --------------------------------
__global__ void __launch_bounds__(256)
agg128_bias(const float* __restrict__ xw, const float* __restrict__ bias,
            float* __restrict__ out, int n)
{
    int node = (blockIdx.x * 256 + threadIdx.x) >> 5;
    int lane = threadIdx.x & 31;
    if (node >= n) return;

    float dsq = g_dinv[node];
    dsq *= dsq;
    const float4* base = (const float4*)xw;
    float4 tv = base[(size_t)node * 32 + lane];
    float4 acc = make_float4(tv.x * dsq, tv.y * dsq, tv.z * dsq, tv.w * dsq);

    int j   = g_rowptr[node];
    int end = j + g_cnt[node];
    for (; j + 8 <= end; j += 8) {
        int2 e[8];
        #pragma unroll
        for (int q = 0; q < 8; q++) e[q] = g_csr[j + q];
        float4 p[8];
        #pragma unroll
        for (int q = 0; q < 8; q++) p[q] = base[(size_t)e[q].x * 32 + lane];
        #pragma unroll
        for (int q = 0; q < 8; q++) {
            float w = __int_as_float(e[q].y);
            acc.x = fmaf(p[q].x, w, acc.x); acc.y = fmaf(p[q].y, w, acc.y);
            acc.z = fmaf(p[q].z, w, acc.z); acc.w = fmaf(p[q].w, w, acc.w);
        }
    }
    for (; j < end; j++) {
        int2 e = g_csr[j];
        float w = __int_as_float(e.y);
        float4 p = base[(size_t)e.x * 32 + lane];
        acc.x = fmaf(p.x, w, acc.x); acc.y = fmaf(p.y, w, acc.y);
        acc.z = fmaf(p.z, w, acc.z); acc.w = fmaf(p.w, w, acc.w);
    }

    float4 b = *((const float4*)bias + lane);
    acc.x += b.x; acc.y += b.y; acc.z += b.z; acc.w += b.w;
    *((float4*)out + (size_t)node * 32 + lane) = acc;
}

// ---------------- launch -----------------------------------------------------
extern "C" void kernel_launch(void* const* d_in, const int* in_sizes, int n_in,
                              void* d_out, int out_size)
{
    const float* emb = (const float*)d_in[0];   // [N, D]
    const float* W1  = (const float*)d_in[1];   // [D, H]
    const float* b1  = (const float*)d_in[2];   // [H]
    const float* W2  = (const float*)d_in[3];   // [H, D]
    const float* b2  = (const float*)d_in[4];   // [D]
    const void*  eix = d_in[5];                 // [2, E] int64 or int32
    float* out = (float*)d_out;                 // [N, D]

    const int D = in_sizes[4];          // 128
    const int H = in_sizes[2];          // 256
    const int N = in_sizes[0] / D;      // 100000
    const int E = in_sizes[5] / 2;      // 1600000
    const int NB = (N + 1023) / 1024;

    float* p_xw2;
    uint32_t *p_a1h, *p_a1l, *p_a2h, *p_a2l;
    ushort_t *p_w1h, *p_w1l, *p_w2h, *p_w2l;
    cudaGetSymbolAddress((void**)&p_xw2, g_xw2);
    cudaGetSymbolAddress((void**)&p_a1h, g_a1h);
    cudaGetSymbolAddress((void**)&p_a1l, g_a1l);
    cudaGetSymbolAddress((void**)&p_a2h, g_a2h);
    cudaGetSymbolAddress((void**)&p_a2l, g_a2l);
    cudaGetSymbolAddress((void**)&p_w1h, g_w1h);
    cudaGetSymbolAddress((void**)&p_w1l, g_w1l);
    cudaGetSymbolAddress((void**)&p_w2h, g_w2h);
    cudaGetSymbolAddress((void**)&p_w2l, g_w2l);

    // ---- graph prep ----
    zero_detect_kernel<<<(N + 255) / 256, 256>>>((const unsigned int*)eix, N);
    count_kernel<<<(E + 255) / 256, 256>>>(eix, E);
    scanblock_dinv_kernel<<<NB, 1024>>>(N);
    add_offsets_kernel<<<(N + 255) / 256, 256>>>(N, NB);
    csr_fill_kernel<<<(E + 255) / 256, 256>>>(eix, E);

    // ---- W images ----
    convert_w_kernel<<<(D * H + 255) / 256, 256>>>(W1, p_w1h, p_w1l, H, D);
    convert_w_kernel<<<(H * D + 255) / 256, 256>>>(W2, p_w2h, p_w2l, D, H);

    // ---- layer 1: a1 = split(agg(emb)); a2 = split(relu(a1 @ W1 + b1)) ----
    agg_split<<<(N + 7) / 8, 256>>>(emb, N);
    {
        dim3 grid(HH / 128, (N + 127) / 128);
        gemm_pre<DD, HH, true><<<grid, 256>>>(
            p_a1h, p_a1l, p_w1h, p_w1l, b1, nullptr, p_a2h, p_a2l, N);
    }

    // ---- layer 2: xw2 = a2 @ W2; out = agg(xw2) + b2 ----
    {
        dim3 grid(DD / 128, (N + 127) / 128);
        gemm_pre<HH, DD, false><<<grid, 256>>>(
            p_a2h, p_a2l, p_w2h, p_w2l, nullptr, p_xw2, nullptr, nullptr, N);
    }
    agg128_bias<<<(N + 7) / 8, 256>>>(p_xw2, b2, out, N);
}

// round 9
// speedup vs baseline: 1.1219x; 1.1219x over previous
#include <cuda_runtime.h>
#include <cuda_bf16.h>
#include <cstdint>

// Problem constants (GCNEncoder_55052890800619)
#define NN 100000
#define DD 128
#define HH 256
#define EE 1600000

// ---------------- scratch (device globals; no allocations allowed) ----------
__device__ int   g_is64;
__device__ int   g_cnt[NN];
__device__ int   g_rowptr[NN];
__device__ int   g_cursor[NN];
__device__ float g_dinv[NN];
__device__ int   g_bsums[128];
__device__ __align__(16) int2  g_csr[EE];                  // 12.8 MB
__device__ __align__(16) float g_aggemb[(size_t)NN * DD];  // 51.2 MB  agg(emb)
__device__ __align__(16) float g_x     [(size_t)NN * HH];  // 102.4 MB
__device__ __align__(16) float g_xw2   [(size_t)NN * DD];  // 51.2 MB

// ---------------- prep kernels ----------------------------------------------
__global__ void zero_detect_kernel(const unsigned int* __restrict__ p, int n) {
    int i = blockIdx.x * blockDim.x + threadIdx.x;
    if (i < n) g_cnt[i] = 0;
    if (blockIdx.x == 0 && threadIdx.x < 32) {
        int any = 0;
        #pragma unroll
        for (int q = 0; q < 2; q++) {
            long long j = (long long)(threadIdx.x * 2 + q) * 24999 + 7;
            any |= (p[2 * j + 1] != 0u);
        }
        any = __any_sync(0xffffffffu, any);
        if (threadIdx.x == 0) g_is64 = any ? 0 : 1;
    }
}

__device__ __forceinline__ int2 load_edge(const void* eptr, int E, int e, int is64) {
    int2 r;
    if (is64) {
        const long long* q = (const long long*)eptr;
        r.x = (int)q[e];
        r.y = (int)q[(size_t)E + e];
    } else {
        const int* q = (const int*)eptr;
        r.x = q[e];
        r.y = q[(size_t)E + e];
    }
    return r;
}

__global__ void count_kernel(const void* __restrict__ eptr, int E) {
    int e = blockIdx.x * blockDim.x + threadIdx.x;
    if (e >= E) return;
    int d;
    if (g_is64) d = (int)(((const long long*)eptr)[(size_t)E + e]);
    else        d = ((const int*)eptr)[(size_t)E + e];
    atomicAdd(&g_cnt[d], 1);
}

__global__ void scanblock_dinv_kernel(int n) {
    __shared__ int sh[1024];
    int gid = blockIdx.x * 1024 + threadIdx.x;
    int v = (gid < n) ? g_cnt[gid] : 0;
    if (gid < n) g_dinv[gid] = rsqrtf((float)v + 1.0f);
    sh[threadIdx.x] = v;
    __syncthreads();
    for (int off = 1; off < 1024; off <<= 1) {
        int t = (threadIdx.x >= (unsigned)off) ? sh[threadIdx.x - off] : 0;
        __syncthreads();
        sh[threadIdx.x] += t;
        __syncthreads();
    }
    if (gid < n) g_rowptr[gid] = sh[threadIdx.x] - v;
    if (threadIdx.x == 1023) g_bsums[blockIdx.x] = sh[1023];
}

__global__ void add_offsets_kernel(int n, int nb) {
    __shared__ int sh[128];
    int tid = threadIdx.x;
    if (tid < 128) sh[tid] = (tid < nb) ? g_bsums[tid] : 0;
    __syncthreads();
    for (int off = 1; off < 128; off <<= 1) {
        int t = (tid >= (unsigned)off && tid < 128) ? sh[tid - off] : 0;
        __syncthreads();
        if (tid < 128) sh[tid] += t;
        __syncthreads();
    }
    int i = blockIdx.x * 256 + tid;
    if (i >= n) return;
    int j = i >> 10;
    int off = (j == 0) ? 0 : sh[j - 1];
    int r = g_rowptr[i] + off;
    g_rowptr[i] = r;
    g_cursor[i] = r;
}

__global__ void csr_fill_kernel(const void* __restrict__ eptr, int E) {
    int e = blockIdx.x * blockDim.x + threadIdx.x;
    if (e >= E) return;
    int2 sd = load_edge(eptr, E, e, g_is64);
    int pos = atomicAdd(&g_cursor[sd.y], 1);
    float w = g_dinv[sd.x] * g_dinv[sd.y];
    g_csr[pos] = make_int2(sd.x, __float_as_int(w));
}

// ---------------- bf16 split helpers ----------------------------------------
__device__ __forceinline__ void split_pack(float x0, float x1,
                                           uint32_t& hi, uint32_t& lo) {
    uint32_t h;
    asm("cvt.rn.bf16x2.f32 %0, %1, %2;" : "=r"(h) : "f"(x1), "f"(x0));
    float e0 = x0 - __uint_as_float(h << 16);
    float e1 = x1 - __uint_as_float(h & 0xffff0000u);
    asm("cvt.rn.bf16x2.f32 %0, %1, %2;" : "=r"(lo) : "f"(e1), "f"(e0));
    hi = h;
}

__device__ __forceinline__ void mma16(float* c, const uint32_t* a, const uint32_t* b) {
    asm volatile(
        "mma.sync.aligned.m16n8k16.row.col.f32.bf16.bf16.f32 "
        "{%0,%1,%2,%3}, {%4,%5,%6,%7}, {%8,%9}, {%0,%1,%2,%3};"
        : "+f"(c[0]), "+f"(c[1]), "+f"(c[2]), "+f"(c[3])
        : "r"(a[0]), "r"(a[1]), "r"(a[2]), "r"(a[3]), "r"(b[0]), "r"(b[1]));
}

// kpair (0..7) -> smem column (pairs (t, t+4) adjacent -> one LDS.64/frag)
__device__ __forceinline__ int colmap(int kp) {
    return ((kp & 3) << 1) | ((kp >> 2) & 1);
}

// ---------------- GEMM: software-pipelined, bf16x2-split (3 MMA terms) -------
// Block 128x128, BK=16, 256 threads = 8 warps, warp tile 64x32, 2 CTAs/SM.
// Double-buffered smem; next tile prefetched to regs during compute.
#define GSTR 10

template <bool RELU_BIAS>
__global__ void __launch_bounds__(256, 2)
gemm_bf16x2(const float* __restrict__ A, const float* __restrict__ B,
            const float* __restrict__ bias, float* __restrict__ C,
            int M, int N, int K)
{
    __shared__ uint32_t Ahi[2][128][GSTR], Alo[2][128][GSTR];
    __shared__ uint32_t Bhi[2][128][GSTR], Blo[2][128][GSTR];

    const int tid  = threadIdx.x;
    const int wid  = tid >> 5;
    const int lane = tid & 31;
    const int g    = lane >> 2;
    const int t    = lane & 3;
    const int brow = blockIdx.y * 128;
    const int bcol = blockIdx.x * 128;
    const int wm   = (wid >> 2) * 64;   // 0 or 64
    const int wn   = (wid & 3) * 32;    // 0,32,64,96

    // loader indices
    const int am0  = tid >> 2;          // A row for q=0 (0..63)
    const int akq0 = tid & 3;           // A float4-k for q=0
    const int bkp  = tid >> 5;          // B kpair 0..7
    const int bn4  = tid & 31;          // B float4-n

    const int ngrp = K >> 4;

    float acc[4][4][4];
    #pragma unroll
    for (int mt = 0; mt < 4; mt++)
        #pragma unroll
        for (int nt = 0; nt < 4; nt++)
            #pragma unroll
            for (int i = 0; i < 4; i++) acc[mt][nt][i] = 0.0f;

    float4 va0, va1, vb0, vb1;

    // ---- tile fetch (LDG only) ----
    auto fetch = [&](int grp) {
        int k0 = grp * 16;
        int r0 = brow + am0;
        int r1 = brow + am0 + 64;
        va0 = make_float4(0.f, 0.f, 0.f, 0.f);
        va1 = make_float4(0.f, 0.f, 0.f, 0.f);
        if (r0 < M) va0 = *(const float4*)(A + (size_t)r0 * K + k0 + akq0 * 4);
        if (r1 < M) va1 = *(const float4*)(A + (size_t)r1 * K + k0 + akq0 * 4);
        const float* br = B + (size_t)(k0 + 2 * bkp) * N + bcol + bn4 * 4;
        vb0 = *(const float4*)br;
        vb1 = *(const float4*)(br + N);
    };
    // ---- split + store to smem buffer ----
    auto stage = [&](int buf) {
        uint32_t h0, l0, h1, l1;
        split_pack(va0.x, va0.y, h0, l0);
        split_pack(va0.z, va0.w, h1, l1);
        int c0 = colmap(2 * akq0), c1 = colmap(2 * akq0 + 1);
        Ahi[buf][am0][c0] = h0; Alo[buf][am0][c0] = l0;
        Ahi[buf][am0][c1] = h1; Alo[buf][am0][c1] = l1;
        split_pack(va1.x, va1.y, h0, l0);
        split_pack(va1.z, va1.w, h1, l1);
        Ahi[buf][am0 + 64][c0] = h0; Alo[buf][am0 + 64][c0] = l0;
        Ahi[buf][am0 + 64][c1] = h1; Alo[buf][am0 + 64][c1] = l1;
        int cb = colmap(bkp);
        uint32_t h, l;
        split_pack(vb0.x, vb1.x, h, l); Bhi[buf][bn4 * 4 + 0][cb] = h; Blo[buf][bn4 * 4 + 0][cb] = l;
        split_pack(vb0.y, vb1.y, h, l); Bhi[buf][bn4 * 4 + 1][cb] = h; Blo[buf][bn4 * 4 + 1][cb] = l;
        split_pack(vb0.z, vb1.z, h, l); Bhi[buf][bn4 * 4 + 2][cb] = h; Blo[buf][bn4 * 4 + 2][cb] = l;
        split_pack(vb0.w, vb1.w, h, l); Bhi[buf][bn4 * 4 + 3][cb] = h; Blo[buf][bn4 * 4 + 3][cb] = l;
    };

    // prologue
    fetch(0);
    stage(0);
    __syncthreads();

    for (int grp = 0; grp < ngrp; grp++) {
        int cur = grp & 1;
        if (grp + 1 < ngrp) fetch(grp + 1);   // LDGs in flight during compute

        {
            const int cb = 2 * t;
            uint32_t ah[4][4], al[4][4];
            #pragma unroll
            for (int mt = 0; mt < 4; mt++) {
                int r = wm + mt * 16;
                uint2 p0 = *(const uint2*)&Ahi[cur][r + g    ][cb];
                uint2 p1 = *(const uint2*)&Ahi[cur][r + g + 8][cb];
                ah[mt][0] = p0.x; ah[mt][2] = p0.y;
                ah[mt][1] = p1.x; ah[mt][3] = p1.y;
                uint2 q0 = *(const uint2*)&Alo[cur][r + g    ][cb];
                uint2 q1 = *(const uint2*)&Alo[cur][r + g + 8][cb];
                al[mt][0] = q0.x; al[mt][2] = q0.y;
                al[mt][1] = q1.x; al[mt][3] = q1.y;
            }
            #pragma unroll
            for (int nt = 0; nt < 4; nt++) {
                uint2 bh2 = *(const uint2*)&Bhi[cur][wn + nt * 8 + g][cb];
                uint2 bl2 = *(const uint2*)&Blo[cur][wn + nt * 8 + g][cb];
                uint32_t bh[2] = {bh2.x, bh2.y};
                uint32_t bl[2] = {bl2.x, bl2.y};
                #pragma unroll
                for (int mt = 0; mt < 4; mt++) {
                    mma16(acc[mt][nt], ah[mt], bh);
                    mma16(acc[mt][nt], ah[mt], bl);
                    mma16(acc[mt][nt], al[mt], bh);
                }
            }
        }

        if (grp + 1 < ngrp) stage(cur ^ 1);
        __syncthreads();
    }

    // epilogue: optional bias+relu, float2 stores
    #pragma unroll
    for (int nt = 0; nt < 4; nt++) {
        int col = bcol + wn + nt * 8 + 2 * t;
        float b0 = 0.f, b1 = 0.f;
        if (RELU_BIAS) { b0 = bias[col]; b1 = bias[col + 1]; }
        #pragma unroll
        for (int mt = 0; mt < 4; mt++) {
            int r0 = brow + wm + mt * 16 + g;
            float2 v0 = make_float2(acc[mt][nt][0] + b0, acc[mt][nt][1] + b1);
            float2 v1 = make_float2(acc[mt][nt][2] + b0, acc[mt][nt][3] + b1);
            if (RELU_BIAS) {
                v0.x = fmaxf(v0.x, 0.f); v0.y = fmaxf(v0.y, 0.f);
                v1.x = fmaxf(v1.x, 0.f); v1.y = fmaxf(v1.y, 0.f);
            }
            if (r0 < M)     *(float2*)(C + (size_t)r0 * N + col) = v0;
            if (r0 + 8 < M) *(float2*)(C + (size_t)(r0 + 8) * N + col) = v1;
        }
    }
}

// ---------------- aggregation (128 cols): warp per node, MLP=8 --------------
template <bool ADD_BIAS>
__global__ void __launch_bounds__(256)
agg128(const float* __restrict__ xw, const float* __restrict__ bias,
       float* __restrict__ out, int n)
{
    int node = (blockIdx.x * 256 + threadIdx.x) >> 5;
    int lane = threadIdx.x & 31;
    if (node >= n) return;

    float dsq = g_dinv[node];
    dsq *= dsq;
    const float4* base = (const float4*)xw;
    float4 tv = base[(size_t)node * 32 + lane];
    float4 acc = make_float4(tv.x * dsq, tv.y * dsq, tv.z * dsq, tv.w * dsq);

    int j   = g_rowptr[node];
    int end = j + g_cnt[node];

    for (; j + 8 <= end; j += 8) {
        int2 e[8];
        #pragma unroll
        for (int q = 0; q < 8; q++) e[q] = g_csr[j + q];
        float4 p[8];
        #pragma unroll
        for (int q = 0; q < 8; q++) p[q] = base[(size_t)e[q].x * 32 + lane];
        #pragma unroll
        for (int q = 0; q < 8; q++) {
            float w = __int_as_float(e[q].y);
            acc.x = fmaf(p[q].x, w, acc.x); acc.y = fmaf(p[q].y, w, acc.y);
            acc.z = fmaf(p[q].z, w, acc.z); acc.w = fmaf(p[q].w, w, acc.w);
        }
    }
    if (j + 4 <= end) {
        int2 e[4];
        #pragma unroll
        for (int q = 0; q < 4; q++) e[q] = g_csr[j + q];
        float4 p[4];
        #pragma unroll
        for (int q = 0; q < 4; q++) p[q] = base[(size_t)e[q].x * 32 + lane];
        #pragma unroll
        for (int q = 0; q < 4; q++) {
            float w = __int_as_float(e[q].y);
            acc.x = fmaf(p[q].x, w, acc.x); acc.y = fmaf(p[q].y, w, acc.y);
            acc.z = fmaf(p[q].z, w, acc.z); acc.w = fmaf(p[q].w, w, acc.w);
        }
        j += 4;
    }
    for (; j < end; j++) {
        int2 e = g_csr[j];
        float w = __int_as_float(e.y);
        float4 p = base[(size_t)e.x * 32 + lane];
        acc.x = fmaf(p.x, w, acc.x); acc.y = fmaf(p.y, w, acc.y);
        acc.z = fmaf(p.z, w, acc.z); acc.w = fmaf(p.w, w, acc.w);
    }

    if (ADD_BIAS) {
        float4 b = *((const float4*)bias + lane);
        acc.x += b.x; acc.y += b.y; acc.z += b.z; acc.w += b.w;
    }
    *((float4*)out + (size_t)node * 32 + lane) = acc;
}

// ---------------- launch -----------------------------------------------------
extern "C" void kernel_launch(void* const* d_in, const int* in_sizes, int n_in,
                              void* d_out, int out_size)
{
    const float* emb = (const float*)d_in[0];   // [N, D]
    const float* W1  = (const float*)d_in[1];   // [D, H]
    const float* b1  = (const float*)d_in[2];   // [H]
    const float* W2  = (const float*)d_in[3];   // [H, D]
    const float* b2  = (const float*)d_in[4];   // [D]
    const void*  eix = d_in[5];                 // [2, E] int64 or int32
    float* out = (float*)d_out;                 // [N, D]

    const int D = in_sizes[4];          // 128
    const int H = in_sizes[2];          // 256
    const int N = in_sizes[0] / D;      // 100000
    const int E = in_sizes[5] / 2;      // 1600000
    const int NB = (N + 1023) / 1024;

    float *p_aggemb, *p_x, *p_xw2;
    cudaGetSymbolAddress((void**)&p_aggemb, g_aggemb);
    cudaGetSymbolAddress((void**)&p_x,      g_x);
    cudaGetSymbolAddress((void**)&p_xw2,    g_xw2);

    // ---- graph prep (5 kernels) ----
    zero_detect_kernel<<<(N + 255) / 256, 256>>>((const unsigned int*)eix, N);
    count_kernel<<<(E + 255) / 256, 256>>>(eix, E);
    scanblock_dinv_kernel<<<NB, 1024>>>(N);
    add_offsets_kernel<<<(N + 255) / 256, 256>>>(N, NB);
    csr_fill_kernel<<<(E + 255) / 256, 256>>>(eix, E);

    // ---- layer 1: aggemb = agg(emb); x = relu(aggemb @ W1 + b1) ----
    agg128<false><<<(N + 7) / 8, 256>>>(emb, nullptr, p_aggemb, N);
    {
        dim3 grid(H / 128, (N + 127) / 128);
        gemm_bf16x2<true><<<grid, 256>>>(p_aggemb, W1, b1, p_x, N, H, D);
    }

    // ---- layer 2: xw2 = x @ W2; out = agg(xw2) + b2 ----
    {
        dim3 grid(D / 128, (N + 127) / 128);
        gemm_bf16x2<false><<<grid, 256>>>(p_x, W2, nullptr, p_xw2, N, D, H);
    }
    agg128<true><<<(N + 7) / 8, 256>>>(p_xw2, b2, out, N);
}

// round 11
// speedup vs baseline: 1.1314x; 1.0084x over previous
#include <cuda_runtime.h>
#include <cuda_bf16.h>
#include <cstdint>

// Problem constants (GCNEncoder_55052890800619)
#define NN 100000
#define DD 128
#define HH 256
#define EE 1600000

// ---------------- scratch (device globals; no allocations allowed) ----------
__device__ int   g_cnt[NN];
__device__ int   g_rowptr[NN];
__device__ int   g_cursor[NN];
__device__ float g_dinv[NN];
__device__ int   g_chain[128];               // scan aggregates (value+1; 0 = unpublished)
__device__ __align__(16) int2  g_csr[EE];                  // 12.8 MB
__device__ __align__(16) float g_aggemb[(size_t)NN * DD];  // 51.2 MB  agg(emb)
__device__ __align__(16) float g_x     [(size_t)NN * HH];  // 102.4 MB
__device__ __align__(16) float g_xw2   [(size_t)NN * DD];  // 51.2 MB

// ---------------- per-block edge dtype detection -----------------------------
// int64 edges (values < 2^31, non-negative) have all-zero odd 32-bit words.
// 64 samples of random odd words being zero for int32 data is impossible.
__device__ __forceinline__ int block_detect_is64(const unsigned int* __restrict__ p,
                                                 int* s_is64) {
    if (threadIdx.x < 32) {
        int any = 0;
        #pragma unroll
        for (int q = 0; q < 2; q++) {
            long long j = (long long)(threadIdx.x * 2 + q) * 24999 + 7;  // < 1.6M
            any |= (p[2 * j + 1] != 0u);
        }
        any = __any_sync(0xffffffffu, any);
        if (threadIdx.x == 0) *s_is64 = any ? 0 : 1;
    }
    __syncthreads();
    return *s_is64;
}

__device__ __forceinline__ int2 load_edge(const void* eptr, int E, int e, int is64) {
    int2 r;
    if (is64) {
        const long long* q = (const long long*)eptr;
        r.x = (int)q[e];
        r.y = (int)q[(size_t)E + e];
    } else {
        const int* q = (const int*)eptr;
        r.x = q[e];
        r.y = q[(size_t)E + e];
    }
    return r;
}

// ---------------- prep kernels (3 launches) ----------------------------------
// 1) degree count (dst half only) + zero the scan-chain slots (block 0)
__global__ void count_kernel(const unsigned int* __restrict__ eptr, int E) {
    __shared__ int s_is64;
    int is64 = block_detect_is64(eptr, &s_is64);
    if (blockIdx.x == 0 && threadIdx.x < 128) g_chain[threadIdx.x] = 0;
    int e = blockIdx.x * blockDim.x + threadIdx.x;
    if (e >= E) return;
    int d;
    if (is64) d = (int)(((const long long*)eptr)[(size_t)E + e]);
    else      d = ((const int*)eptr)[(size_t)E + e];
    atomicAdd(&g_cnt[d], 1);
}

// 2) fused exclusive scan (publish-aggregate + parallel lookback) + dinv + cursor
//    All <=98 blocks of 1024 threads are co-resident on 148 SMs -> safe spins.
__global__ void scan_fused_kernel(int n) {
    __shared__ int sh[1024];
    __shared__ int agg[128];
    __shared__ int s_prefix;
    const int b   = blockIdx.x;
    const int tid = threadIdx.x;
    const int gid = b * 1024 + tid;

    int v = (gid < n) ? g_cnt[gid] : 0;
    if (gid < n) g_dinv[gid] = rsqrtf((float)v + 1.0f);
    sh[tid] = v;
    __syncthreads();
    for (int off = 1; off < 1024; off <<= 1) {
        int t = (tid >= (unsigned)off) ? sh[tid - off] : 0;
        __syncthreads();
        sh[tid] += t;
        __syncthreads();
    }
    // publish own aggregate immediately (before any waiting)
    if (tid == 0) atomicExch(&g_chain[b], sh[1023] + 1);
    // parallel lookback: thread i spins on predecessor i
    if (tid < 128) agg[tid] = 0;
    if (tid < b) {
        int p;
        do { p = atomicAdd(&g_chain[tid], 0); } while (p == 0);
        agg[tid] = p - 1;
    }
    __syncthreads();
    if (tid == 0) {
        int s = 0;
        #pragma unroll 4
        for (int i = 0; i < b; i++) s += agg[i];
        s_prefix = s;
    }
    __syncthreads();
    if (gid < n) {
        int r = s_prefix + sh[tid] - v;   // exclusive global prefix
        g_rowptr[gid] = r;
        g_cursor[gid] = r;
    }
}

// 3) scatter edges into packed CSR (one 8B store per edge)
__global__ void csr_fill_kernel(const unsigned int* __restrict__ eptr, int E) {
    __shared__ int s_is64;
    int is64 = block_detect_is64(eptr, &s_is64);
    int e = blockIdx.x * blockDim.x + threadIdx.x;
    if (e >= E) return;
    int2 sd = load_edge(eptr, E, e, is64);
    int pos = atomicAdd(&g_cursor[sd.y], 1);
    float w = g_dinv[sd.x] * g_dinv[sd.y];
    g_csr[pos] = make_int2(sd.x, __float_as_int(w));
}

// ---------------- bf16 split helpers ----------------------------------------
__device__ __forceinline__ void split_pack(float x0, float x1,
                                           uint32_t& hi, uint32_t& lo) {
    uint32_t h;
    asm("cvt.rn.bf16x2.f32 %0, %1, %2;" : "=r"(h) : "f"(x1), "f"(x0));
    float e0 = x0 - __uint_as_float(h << 16);
    float e1 = x1 - __uint_as_float(h & 0xffff0000u);
    asm("cvt.rn.bf16x2.f32 %0, %1, %2;" : "=r"(lo) : "f"(e1), "f"(e0));
    hi = h;
}

__device__ __forceinline__ void mma16(float* c, const uint32_t* a, const uint32_t* b) {
    asm volatile(
        "mma.sync.aligned.m16n8k16.row.col.f32.bf16.bf16.f32 "
        "{%0,%1,%2,%3}, {%4,%5,%6,%7}, {%8,%9}, {%0,%1,%2,%3};"
        : "+f"(c[0]), "+f"(c[1]), "+f"(c[2]), "+f"(c[3])
        : "r"(a[0]), "r"(a[1]), "r"(a[2]), "r"(a[3]), "r"(b[0]), "r"(b[1]));
}

// kpair (0..7) -> smem column (pairs (t, t+4) adjacent -> one LDS.64/frag)
__device__ __forceinline__ int colmap(int kp) {
    return ((kp & 3) << 1) | ((kp >> 2) & 1);
}

// ---------------- GEMM: software-pipelined, bf16x2-split (3 MMA terms) -------
// Block 128x128, BK=16, 256 threads = 8 warps, warp tile 64x32, 2 CTAs/SM.
#define GSTR 10

template <bool RELU_BIAS>
__global__ void __launch_bounds__(256, 2)
gemm_bf16x2(const float* __restrict__ A, const float* __restrict__ B,
            const float* __restrict__ bias, float* __restrict__ C,
            int M, int N, int K)
{
    __shared__ uint32_t Ahi[2][128][GSTR], Alo[2][128][GSTR];
    __shared__ uint32_t Bhi[2][128][GSTR], Blo[2][128][GSTR];

    const int tid  = threadIdx.x;
    const int wid  = tid >> 5;
    const int lane = tid & 31;
    const int g    = lane >> 2;
    const int t    = lane & 3;
    const int brow = blockIdx.y * 128;
    const int bcol = blockIdx.x * 128;
    const int wm   = (wid >> 2) * 64;   // 0 or 64
    const int wn   = (wid & 3) * 32;    // 0,32,64,96

    const int am0  = tid >> 2;          // A row for q=0 (0..63)
    const int akq0 = tid & 3;           // A float4-k
    const int bkp  = tid >> 5;          // B kpair 0..7
    const int bn4  = tid & 31;          // B float4-n

    const int ngrp = K >> 4;

    float acc[4][4][4];
    #pragma unroll
    for (int mt = 0; mt < 4; mt++)
        #pragma unroll
        for (int nt = 0; nt < 4; nt++)
            #pragma unroll
            for (int i = 0; i < 4; i++) acc[mt][nt][i] = 0.0f;

    float4 va0, va1, vb0, vb1;

    auto fetch = [&](int grp) {
        int k0 = grp * 16;
        int r0 = brow + am0;
        int r1 = brow + am0 + 64;
        va0 = make_float4(0.f, 0.f, 0.f, 0.f);
        va1 = make_float4(0.f, 0.f, 0.f, 0.f);
        if (r0 < M) va0 = *(const float4*)(A + (size_t)r0 * K + k0 + akq0 * 4);
        if (r1 < M) va1 = *(const float4*)(A + (size_t)r1 * K + k0 + akq0 * 4);
        const float* br = B + (size_t)(k0 + 2 * bkp) * N + bcol + bn4 * 4;
        vb0 = *(const float4*)br;
        vb1 = *(const float4*)(br + N);
    };
    auto stage = [&](int buf) {
        uint32_t h0, l0, h1, l1;
        split_pack(va0.x, va0.y, h0, l0);
        split_pack(va0.z, va0.w, h1, l1);
        int c0 = colmap(2 * akq0), c1 = colmap(2 * akq0 + 1);
        Ahi[buf][am0][c0] = h0; Alo[buf][am0][c0] = l0;
        Ahi[buf][am0][c1] = h1; Alo[buf][am0][c1] = l1;
        split_pack(va1.x, va1.y, h0, l0);
        split_pack(va1.z, va1.w, h1, l1);
        Ahi[buf][am0 + 64][c0] = h0; Alo[buf][am0 + 64][c0] = l0;
        Ahi[buf][am0 + 64][c1] = h1; Alo[buf][am0 + 64][c1] = l1;
        int cb = colmap(bkp);
        uint32_t h, l;
        split_pack(vb0.x, vb1.x, h, l); Bhi[buf][bn4 * 4 + 0][cb] = h; Blo[buf][bn4 * 4 + 0][cb] = l;
        split_pack(vb0.y, vb1.y, h, l); Bhi[buf][bn4 * 4 + 1][cb] = h; Blo[buf][bn4 * 4 + 1][cb] = l;
        split_pack(vb0.z, vb1.z, h, l); Bhi[buf][bn4 * 4 + 2][cb] = h; Blo[buf][bn4 * 4 + 2][cb] = l;
        split_pack(vb0.w, vb1.w, h, l); Bhi[buf][bn4 * 4 + 3][cb] = h; Blo[buf][bn4 * 4 + 3][cb] = l;
    };

    fetch(0);
    stage(0);
    __syncthreads();

    for (int grp = 0; grp < ngrp; grp++) {
        int cur = grp & 1;
        if (grp + 1 < ngrp) fetch(grp + 1);

        {
            const int cb = 2 * t;
            uint32_t ah[4][4], al[4][4];
            #pragma unroll
            for (int mt = 0; mt < 4; mt++) {
                int r = wm + mt * 16;
                uint2 p0 = *(const uint2*)&Ahi[cur][r + g    ][cb];
                uint2 p1 = *(const uint2*)&Ahi[cur][r + g + 8][cb];
                ah[mt][0] = p0.x; ah[mt][2] = p0.y;
                ah[mt][1] = p1.x; ah[mt][3] = p1.y;
                uint2 q0 = *(const uint2*)&Alo[cur][r + g    ][cb];
                uint2 q1 = *(const uint2*)&Alo[cur][r + g + 8][cb];
                al[mt][0] = q0.x; al[mt][2] = q0.y;
                al[mt][1] = q1.x; al[mt][3] = q1.y;
            }
            #pragma unroll
            for (int nt = 0; nt < 4; nt++) {
                uint2 bh2 = *(const uint2*)&Bhi[cur][wn + nt * 8 + g][cb];
                uint2 bl2 = *(const uint2*)&Blo[cur][wn + nt * 8 + g][cb];
                uint32_t bh[2] = {bh2.x, bh2.y};
                uint32_t bl[2] = {bl2.x, bl2.y};
                #pragma unroll
                for (int mt = 0; mt < 4; mt++) {
                    mma16(acc[mt][nt], ah[mt], bh);
                    mma16(acc[mt][nt], ah[mt], bl);
                    mma16(acc[mt][nt], al[mt], bh);
                }
            }
        }

        if (grp + 1 < ngrp) stage(cur ^ 1);
        __syncthreads();
    }

    #pragma unroll
    for (int nt = 0; nt < 4; nt++) {
        int col = bcol + wn + nt * 8 + 2 * t;
        float b0 = 0.f, b1 = 0.f;
        if (RELU_BIAS) { b0 = bias[col]; b1 = bias[col + 1]; }
        #pragma unroll
        for (int mt = 0; mt < 4; mt++) {
            int r0 = brow + wm + mt * 16 + g;
            float2 v0 = make_float2(acc[mt][nt][0] + b0, acc[mt][nt][1] + b1);
            float2 v1 = make_float2(acc[mt][nt][2] + b0, acc[mt][nt][3] + b1);
            if (RELU_BIAS) {
                v0.x = fmaxf(v0.x, 0.f); v0.y = fmaxf(v0.y, 0.f);
                v1.x = fmaxf(v1.x, 0.f); v1.y = fmaxf(v1.y, 0.f);
            }
            if (r0 < M)     *(float2*)(C + (size_t)r0 * N + col) = v0;
            if (r0 + 8 < M) *(float2*)(C + (size_t)(r0 + 8) * N + col) = v1;
        }
    }
}

// ---------------- aggregation (128 cols): warp per node, MLP=8 --------------
template <bool ADD_BIAS>
__global__ void __launch_bounds__(256)
agg128(const float* __restrict__ xw, const float* __restrict__ bias,
       float* __restrict__ out, int n)
{
    int node = (blockIdx.x * 256 + threadIdx.x) >> 5;
    int lane = threadIdx.x & 31;
    if (node >= n) return;

    float dsq = g_dinv[node];
    dsq *= dsq;
    const float4* base = (const float4*)xw;
    float4 tv = base[(size_t)node * 32 + lane];
    float4 acc = make_float4(tv.x * dsq, tv.y * dsq, tv.z * dsq, tv.w * dsq);

    int j   = g_rowptr[node];
    int end = j + g_cnt[node];

    for (; j + 8 <= end; j += 8) {
        int2 e[8];
        #pragma unroll
        for (int q = 0; q < 8; q++) e[q] = g_csr[j + q];
        float4 p[8];
        #pragma unroll
        for (int q = 0; q < 8; q++) p[q] = base[(size_t)e[q].x * 32 + lane];
        #pragma unroll
        for (int q = 0; q < 8; q++) {
            float w = __int_as_float(e[q].y);
            acc.x = fmaf(p[q].x, w, acc.x); acc.y = fmaf(p[q].y, w, acc.y);
            acc.z = fmaf(p[q].z, w, acc.z); acc.w = fmaf(p[q].w, w, acc.w);
        }
    }
    if (j + 4 <= end) {
        int2 e[4];
        #pragma unroll
        for (int q = 0; q < 4; q++) e[q] = g_csr[j + q];
        float4 p[4];
        #pragma unroll
        for (int q = 0; q < 4; q++) p[q] = base[(size_t)e[q].x * 32 + lane];
        #pragma unroll
        for (int q = 0; q < 4; q++) {
            float w = __int_as_float(e[q].y);
            acc.x = fmaf(p[q].x, w, acc.x); acc.y = fmaf(p[q].y, w, acc.y);
            acc.z = fmaf(p[q].z, w, acc.z); acc.w = fmaf(p[q].w, w, acc.w);
        }
        j += 4;
    }
    for (; j < end; j++) {
        int2 e = g_csr[j];
        float w = __int_as_float(e.y);
        float4 p = base[(size_t)e.x * 32 + lane];
        acc.x = fmaf(p.x, w, acc.x); acc.y = fmaf(p.y, w, acc.y);
        acc.z = fmaf(p.z, w, acc.z); acc.w = fmaf(p.w, w, acc.w);
    }

    if (ADD_BIAS) {
        float4 b = *((const float4*)bias + lane);
        acc.x += b.x; acc.y += b.y; acc.z += b.z; acc.w += b.w;
    }
    *((float4*)out + (size_t)node * 32 + lane) = acc;
}

// ---------------- launch -----------------------------------------------------
extern "C" void kernel_launch(void* const* d_in, const int* in_sizes, int n_in,
                              void* d_out, int out_size)
{
    const float* emb = (const float*)d_in[0];   // [N, D]
    const float* W1  = (const float*)d_in[1];   // [D, H]
    const float* b1  = (const float*)d_in[2];   // [H]
    const float* W2  = (const float*)d_in[3];   // [H, D]
    const float* b2  = (const float*)d_in[4];   // [D]
    const void*  eix = d_in[5];                 // [2, E] int64 or int32
    float* out = (float*)d_out;                 // [N, D]

    const int D = in_sizes[4];          // 128
    const int H = in_sizes[2];          // 256
    const int N = in_sizes[0] / D;      // 100000
    const int E = in_sizes[5] / 2;      // 1600000
    const int NB = (N + 1023) / 1024;   // 98 scan blocks (co-resident)

    float *p_aggemb, *p_x, *p_xw2;
    int* p_cnt;
    cudaGetSymbolAddress((void**)&p_aggemb, g_aggemb);
    cudaGetSymbolAddress((void**)&p_x,      g_x);
    cudaGetSymbolAddress((void**)&p_xw2,    g_xw2);
    cudaGetSymbolAddress((void**)&p_cnt,    g_cnt);

    // ---- graph prep: memset + 3 kernels ----
    cudaMemsetAsync(p_cnt, 0, (size_t)N * sizeof(int));
    count_kernel<<<(E + 255) / 256, 256>>>((const unsigned int*)eix, E);
    scan_fused_kernel<<<NB, 1024>>>(N);
    csr_fill_kernel<<<(E + 255) / 256, 256>>>((const unsigned int*)eix, E);

    // ---- layer 1: aggemb = agg(emb); x = relu(aggemb @ W1 + b1) ----
    agg128<false><<<(N + 7) / 8, 256>>>(emb, nullptr, p_aggemb, N);
    {
        dim3 grid(H / 128, (N + 127) / 128);
        gemm_bf16x2<true><<<grid, 256>>>(p_aggemb, W1, b1, p_x, N, H, D);
    }

    // ---- layer 2: xw2 = x @ W2; out = agg(xw2) + b2 ----
    {
        dim3 grid(D / 128, (N + 127) / 128);
        gemm_bf16x2<false><<<grid, 256>>>(p_x, W2, nullptr, p_xw2, N, D, H);
    }
    agg128<true><<<(N + 7) / 8, 256>>>(p_xw2, b2, out, N);
}